// round 4
// baseline (speedup 1.0000x reference)
#include <cuda_runtime.h>
#include <cuda_bf16.h>
#include <cstdint>

// Problem constants
#define NMAX 100000
#define EMAX 1600000
#define HID 64
#define TOW 4
#define FW 16
#define POST_IN 208
#define LOG17 2.8332133440562162f
#define STD_EPS 1e-5f

// Scratch (static device allocations; no cudaMalloc anywhere)
__device__ int   g_cnt[NMAX];
__device__ int   g_off[NMAX + 1];
__device__ int   g_pos[NMAX];
__device__ int   g_eid[EMAX];
__device__ float g_m[(size_t)EMAX * 64];   // per-edge messages [E,64]

// ---------------- K1: zero histogram ----------------
__global__ void k_zero(int n) {
    int i = blockIdx.x * blockDim.x + threadIdx.x;
    if (i < n) g_cnt[i] = 0;
}

// ---------------- K2: histogram over dst ----------------
__global__ void k_hist(const int* __restrict__ ei, int E) {
    int i = blockIdx.x * blockDim.x + threadIdx.x;
    if (i < E) atomicAdd(&g_cnt[ei[E + i]], 1);
}

// ---------------- K3: single-block exclusive scan ----------------
__global__ void k_scan(int N, int E) {
    __shared__ int sh[1024];
    int tid = threadIdx.x;
    int C = (N + 1023) / 1024;
    int s = tid * C;
    int e = min(s + C, N);
    int sum = 0;
    for (int i = s; i < e; i++) sum += g_cnt[i];
    sh[tid] = sum;
    __syncthreads();
    // Hillis-Steele inclusive scan
    for (int off = 1; off < 1024; off <<= 1) {
        int v = (tid >= off) ? sh[tid - off] : 0;
        __syncthreads();
        sh[tid] += v;
        __syncthreads();
    }
    int run = sh[tid] - sum;  // exclusive
    for (int i = s; i < e; i++) {
        g_off[i] = run;
        g_pos[i] = run;
        run += g_cnt[i];
    }
    if (tid == 0) g_off[N] = E;
}

// ---------------- K4: edge kernel ----------------
// One warp per edge. Lane computes output features (2*lane, 2*lane+1):
// tower t = lane/8, in-tower outputs o0 = (2*lane)%16, o0+1.
// W_pre columns live in registers (96 floats/lane).
__global__ void __launch_bounds__(128, 3) k_edge(
    const float* __restrict__ x, const int* __restrict__ ei,
    const float* __restrict__ eattr, const float* __restrict__ W_edge,
    const float* __restrict__ b_edge, const float* __restrict__ W_pre,
    const float* __restrict__ b_pre, int E)
{
    const int lane = threadIdx.x & 31;
    const int warp = blockIdx.x * (blockDim.x >> 5) + (threadIdx.x >> 5);
    const int nwarps = gridDim.x * (blockDim.x >> 5);
    const int t = lane >> 3;
    const int o0 = (2 * lane) & 15;

    // Register-resident W_pre columns for this lane's two outputs
    float Wa[48], Wb[48];
#pragma unroll
    for (int j = 0; j < 48; j++) {
        Wa[j] = W_pre[(t * 48 + j) * 16 + o0];
        Wb[j] = W_pre[(t * 48 + j) * 16 + o0 + 1];
    }
    const float bp0 = b_pre[t * 16 + o0];
    const float bp1 = b_pre[t * 16 + o0 + 1];

    // Edge-encoder weights for lanes 0..15 (each lane owns one ea channel)
    float we0 = 0.f, we1 = 0.f, we2 = 0.f, we3 = 0.f, be = 0.f;
    if (lane < 16) {
        we0 = W_edge[0 * 16 + lane];
        we1 = W_edge[1 * 16 + lane];
        we2 = W_edge[2 * 16 + lane];
        we3 = W_edge[3 * 16 + lane];
        be  = b_edge[lane];
    }

    for (int e = warp; e < E; e += nwarps) {
        const int src = ei[e];
        const int dst = ei[E + e];

        // x_i = x[dst], x_j = x[src]; load this lane's tower slice (16 floats each)
        const float4* xip = reinterpret_cast<const float4*>(x + (size_t)dst * 64 + t * 16);
        const float4* xjp = reinterpret_cast<const float4*>(x + (size_t)src * 64 + t * 16);
        float xi[16], xj[16];
#pragma unroll
        for (int q = 0; q < 4; q++) {
            float4 a = xip[q];
            xi[4 * q] = a.x; xi[4 * q + 1] = a.y; xi[4 * q + 2] = a.z; xi[4 * q + 3] = a.w;
            float4 b = xjp[q];
            xj[4 * q] = b.x; xj[4 * q + 1] = b.y; xj[4 * q + 2] = b.z; xj[4 * q + 3] = b.w;
        }

        // ea: lanes 0..15 compute their channel, broadcast via shfl
        const float4 ev = *reinterpret_cast<const float4*>(eattr + (size_t)e * 4);
        float ea_own = be + ev.x * we0 + ev.y * we1 + ev.z * we2 + ev.w * we3;

        float a0 = bp0, a1 = bp1;
#pragma unroll
        for (int k = 0; k < 16; k++) {
            float eak = __shfl_sync(0xffffffffu, ea_own, k);
            a0 += xi[k] * Wa[k];
            a1 += xi[k] * Wb[k];
            a0 += xj[k] * Wa[16 + k];
            a1 += xj[k] * Wb[16 + k];
            a0 += eak * Wa[32 + k];
            a1 += eak * Wb[32 + k];
        }

        // Coalesced message write: [E,64], features (2*lane, 2*lane+1)
        reinterpret_cast<float2*>(g_m + (size_t)e * 64)[lane] = make_float2(a0, a1);

        // CSR scatter of edge id
        if (lane == 0) {
            int p = atomicAdd(&g_pos[dst], 1);
            g_eid[p] = e;
        }
    }
}

// ---------------- K5: node kernel ----------------
// One warp per node. Lane owns features (2*lane, 2*lane+1).
// Reduces incident messages in registers, then fused post-MLP + linear + ReLU.
__global__ void __launch_bounds__(256) k_node(
    const float* __restrict__ x, const float* __restrict__ W_post,
    const float* __restrict__ b_post, const float* __restrict__ W_lin,
    const float* __restrict__ b_lin, float* __restrict__ out, int N)
{
    __shared__ float in_s[8][4][212];  // padded stride avoids bank conflicts
    __shared__ float post_s[8][64];

    const int lane = threadIdx.x & 31;
    const int wid = threadIdx.x >> 5;
    const int warp = blockIdx.x * 8 + wid;
    const int nw = gridDim.x * 8;
    const int t = lane >> 3;
    const int o0 = (2 * lane) & 15;

    for (int n = warp; n < N; n += nw) {
        const int base = g_off[n];
        const int end = g_off[n + 1];
        const int cnt = end - base;

        float s0 = 0.f, s1 = 0.f, q0 = 0.f, q1 = 0.f;
        float mn0 = 1e30f, mn1 = 1e30f, mx0 = -1e30f, mx1 = -1e30f;
#pragma unroll 4
        for (int i = base; i < end; i++) {
            int e = g_eid[i];
            float2 v = reinterpret_cast<const float2*>(g_m)[(size_t)e * 32 + lane];
            s0 += v.x; s1 += v.y;
            q0 += v.x * v.x; q1 += v.y * v.y;
            mn0 = fminf(mn0, v.x); mn1 = fminf(mn1, v.y);
            mx0 = fmaxf(mx0, v.x); mx1 = fmaxf(mx1, v.y);
        }

        const float deg = fmaxf((float)cnt, 1.f);
        const float inv = 1.f / deg;
        float mean0 = s0 * inv, mean1 = s1 * inv;
        float std0 = sqrtf(fmaxf(q0 * inv - mean0 * mean0, 0.f) + STD_EPS);
        float std1 = sqrtf(fmaxf(q1 * inv - mean1 * mean1, 0.f) + STD_EPS);
        if (cnt == 0) { mn0 = mn1 = mx0 = mx1 = 0.f; }

        const float logdeg = logf(deg + 1.f);
        const float samp = logdeg * (1.f / LOG17);
        const float satt = LOG17 / logdeg;

        const float2 xv = reinterpret_cast<const float2*>(x + (size_t)n * 64)[lane];

        float* row = in_s[wid][t];
        row[o0] = xv.x;            row[o0 + 1] = xv.y;
        row[16 + o0] = mean0;      row[16 + o0 + 1] = mean1;
        row[32 + o0] = mn0;        row[32 + o0 + 1] = mn1;
        row[48 + o0] = mx0;        row[48 + o0 + 1] = mx1;
        row[64 + o0] = std0;       row[64 + o0 + 1] = std1;
        row[80 + o0] = mean0 * samp;   row[80 + o0 + 1] = mean1 * samp;
        row[96 + o0] = mn0 * samp;     row[96 + o0 + 1] = mn1 * samp;
        row[112 + o0] = mx0 * samp;    row[112 + o0 + 1] = mx1 * samp;
        row[128 + o0] = std0 * samp;   row[128 + o0 + 1] = std1 * samp;
        row[144 + o0] = mean0 * satt;  row[144 + o0 + 1] = mean1 * satt;
        row[160 + o0] = mn0 * satt;    row[160 + o0 + 1] = mn1 * satt;
        row[176 + o0] = mx0 * satt;    row[176 + o0 + 1] = mx1 * satt;
        row[192 + o0] = std0 * satt;   row[192 + o0 + 1] = std1 * satt;
        __syncwarp();

        // post MLP: this lane computes post features (2*lane, 2*lane+1)
        float a0 = b_post[2 * lane];
        float a1 = b_post[2 * lane + 1];
        const float2* Wp2 = reinterpret_cast<const float2*>(W_post);
        const int wb = (o0 >> 1);
#pragma unroll 4
        for (int f = 0; f < POST_IN; f++) {
            float iv = row[f];
            float2 w = Wp2[(t * POST_IN + f) * 8 + wb];
            a0 += iv * w.x;
            a1 += iv * w.y;
        }
        post_s[wid][2 * lane] = a0;
        post_s[wid][2 * lane + 1] = a1;
        __syncwarp();

        // final linear 64x64 + ReLU
        float y0 = b_lin[2 * lane];
        float y1 = b_lin[2 * lane + 1];
        const float2* Wl2 = reinterpret_cast<const float2*>(W_lin);
#pragma unroll
        for (int k = 0; k < 64; k++) {
            float p = post_s[wid][k];
            float2 w = Wl2[k * 32 + lane];
            y0 += p * w.x;
            y1 += p * w.y;
        }
        reinterpret_cast<float2*>(out + (size_t)n * 64)[lane] =
            make_float2(fmaxf(y0, 0.f), fmaxf(y1, 0.f));
        __syncwarp();
    }
}

extern "C" void kernel_launch(void* const* d_in, const int* in_sizes, int n_in,
                              void* d_out, int out_size)
{
    const float* x      = (const float*)d_in[0];
    const int*   ei     = (const int*)d_in[1];
    const float* eattr  = (const float*)d_in[2];
    const float* W_edge = (const float*)d_in[3];
    const float* b_edge = (const float*)d_in[4];
    const float* W_pre  = (const float*)d_in[5];
    const float* b_pre  = (const float*)d_in[6];
    const float* W_post = (const float*)d_in[7];
    const float* b_post = (const float*)d_in[8];
    const float* W_lin  = (const float*)d_in[9];
    const float* b_lin  = (const float*)d_in[10];
    float* out = (float*)d_out;

    const int N = in_sizes[0] / 64;
    const int E = in_sizes[1] / 2;

    k_zero<<<(N + 255) / 256, 256>>>(N);
    k_hist<<<(E + 255) / 256, 256>>>(ei, E);
    k_scan<<<1, 1024>>>(N, E);
    k_edge<<<1480, 128>>>(x, ei, eattr, W_edge, b_edge, W_pre, b_pre, E);
    k_node<<<2048, 256>>>(x, W_post, b_post, W_lin, b_lin, out, N);
}

// round 5
// speedup vs baseline: 3.1524x; 3.1524x over previous
#include <cuda_runtime.h>
#include <cuda_bf16.h>
#include <cstdint>

#define NN 100000
#define EE 1600000
#define LOG17 2.8332133440562162f
#define STD_EPS 1e-5f

// ---- scratch (static device arrays; no allocation anywhere) ----
__device__ int    g_cnt[NN];
__device__ int    g_off[NN + 1];
__device__ int    g_pos[NN];
__device__ int    g_src[EE];
__device__ float4 g_ea[EE];
__device__ float  g_u[(size_t)NN * 64];
__device__ float  g_v[(size_t)NN * 64];
__device__ float  g_agg[(size_t)NN * 256];   // [n][t][stat(4)][16]
__device__ float2 g_scal[NN];                // (samp, satt)
__device__ float  g_WE[256];                 // [t][4][16] folded edge weights
__device__ float  g_BE[64];                  // [t][16]   folded bias (b_edge@C + b_pre)

// ---------------- K1: zero histogram ----------------
__global__ void k_zero(int n) {
    int i = blockIdx.x * blockDim.x + threadIdx.x;
    if (i < n) g_cnt[i] = 0;
}

// ---------------- K2: histogram over dst ----------------
__global__ void k_hist(const int* __restrict__ ei, int E) {
    int i = blockIdx.x * blockDim.x + threadIdx.x;
    if (i < E) atomicAdd(&g_cnt[ei[E + i]], 1);
}

// ---------------- K3: single-block exclusive scan ----------------
__global__ void k_scan(int N, int E) {
    __shared__ int sh[1024];
    int tid = threadIdx.x;
    int C = (N + 1023) / 1024;
    int s = tid * C;
    int e = min(s + C, N);
    int sum = 0;
    for (int i = s; i < e; i++) sum += g_cnt[i];
    sh[tid] = sum;
    __syncthreads();
    for (int off = 1; off < 1024; off <<= 1) {
        int v = (tid >= off) ? sh[tid - off] : 0;
        __syncthreads();
        sh[tid] += v;
        __syncthreads();
    }
    int run = sh[tid] - sum;  // exclusive
    for (int i = s; i < e; i++) {
        g_off[i] = run;
        g_pos[i] = run;
        run += g_cnt[i];
    }
    if (tid == 0) g_off[N] = E;
}

// ---------------- K4: fold edge-encoder through W_pre's ea block ----------------
// WE[t][d][o] = sum_k W_edge[d][k] * W_pre[t][32+k][o]
// BE[t][o]    = b_pre[t][o] + sum_k b_edge[k] * W_pre[t][32+k][o]
__global__ void k_fold(const float* __restrict__ We, const float* __restrict__ be,
                       const float* __restrict__ Wp, const float* __restrict__ bp) {
    int tid = threadIdx.x;            // 256 threads
    int t = tid >> 6, d = (tid >> 4) & 3, o = tid & 15;
    float s = 0.f;
#pragma unroll
    for (int k = 0; k < 16; k++)
        s += We[d * 16 + k] * Wp[(t * 48 + 32 + k) * 16 + o];
    g_WE[t * 64 + d * 16 + o] = s;
    if (d == 0) {
        float b = bp[t * 16 + o];
#pragma unroll
        for (int k = 0; k < 16; k++)
            b += be[k] * Wp[(t * 48 + 32 + k) * 16 + o];
        g_BE[t * 16 + o] = b;
    }
}

// ---------------- K5: per-node u = x@A, v = x@B (per tower) ----------------
__global__ void __launch_bounds__(256) k_uv(const float* __restrict__ x,
                                            const float* __restrict__ Wp, int N) {
    __shared__ float A64[16 * 64], B64[16 * 64];   // [k][g] where g=t*16+o
    int tid = threadIdx.x;
    for (int i = tid; i < 1024; i += 256) {
        int k = i >> 6, g = i & 63, t = g >> 4, o = g & 15;
        A64[i] = Wp[(t * 48 + k) * 16 + o];
        B64[i] = Wp[(t * 48 + 16 + k) * 16 + o];
    }
    __syncthreads();
    int lane = tid & 31, wid = tid >> 5;
    int warp = blockIdx.x * 8 + wid, nw = gridDim.x * 8;
    const float2* A2 = (const float2*)A64;
    const float2* B2 = (const float2*)B64;
    for (int n = warp; n < N; n += nw) {
        float2 xv = ((const float2*)(x + (size_t)n * 64))[lane];
        float u0 = 0.f, u1 = 0.f, v0 = 0.f, v1 = 0.f;
#pragma unroll
        for (int k = 0; k < 16; k++) {
            int srcl = (lane & 24) | (k >> 1);
            float xk = __shfl_sync(0xffffffffu, (k & 1) ? xv.y : xv.x, srcl);
            float2 a = A2[k * 32 + lane];
            float2 b = B2[k * 32 + lane];
            u0 = fmaf(xk, a.x, u0); u1 = fmaf(xk, a.y, u1);
            v0 = fmaf(xk, b.x, v0); v1 = fmaf(xk, b.y, v1);
        }
        ((float2*)(g_u + (size_t)n * 64))[lane] = make_float2(u0, u1);
        ((float2*)(g_v + (size_t)n * 64))[lane] = make_float2(v0, v1);
    }
}

// ---------------- K6: CSR scatter (src + edge_attr reordered by dst) ----------------
__global__ void k_scatter(const int* __restrict__ ei, const float* __restrict__ eattr, int E) {
    int e = blockIdx.x * blockDim.x + threadIdx.x;
    if (e < E) {
        int dst = ei[E + e];
        int p = atomicAdd(&g_pos[dst], 1);
        g_src[p] = ei[e];
        g_ea[p] = ((const float4*)eattr)[e];
    }
}

// ---------------- K7: aggregation (fused on-the-fly messages) ----------------
// One warp per node; lane owns global features (2*lane, 2*lane+1), tower t=lane>>3.
__global__ void __launch_bounds__(256) k_agg(int N) {
    int tid = threadIdx.x, lane = tid & 31, wid = tid >> 5;
    int t = lane >> 3, o0 = (2 * lane) & 15;
    int warp = blockIdx.x * 8 + wid, nw = gridDim.x * 8;

    float2 WEr[4];
#pragma unroll
    for (int d = 0; d < 4; d++)
        WEr[d] = ((const float2*)g_WE)[(t * 64 + d * 16 + o0) >> 1];
    float2 BEr = ((const float2*)g_BE)[lane];

    for (int n = warp; n < N; n += nw) {
        int base = g_off[n], end = g_off[n + 1];
        int cnt = end - base;

        float s0 = 0.f, s1 = 0.f, q0 = 0.f, q1 = 0.f;
        float mn0 = 1e30f, mn1 = 1e30f, mx0 = -1e30f, mx1 = -1e30f;

        int i = base;
        for (; i + 4 <= end; i += 4) {
            int sA = g_src[i], sB = g_src[i + 1], sC = g_src[i + 2], sD = g_src[i + 3];
            float4 eA = g_ea[i], eB = g_ea[i + 1], eC = g_ea[i + 2], eD = g_ea[i + 3];
            float2 vA = ((const float2*)(g_v + (size_t)sA * 64))[lane];
            float2 vB = ((const float2*)(g_v + (size_t)sB * 64))[lane];
            float2 vC = ((const float2*)(g_v + (size_t)sC * 64))[lane];
            float2 vD = ((const float2*)(g_v + (size_t)sD * 64))[lane];
#define PROC(ea, vv)                                                            \
            {                                                                   \
                float m0 = vv.x, m1 = vv.y;                                     \
                m0 = fmaf(ea.x, WEr[0].x, m0); m1 = fmaf(ea.x, WEr[0].y, m1);   \
                m0 = fmaf(ea.y, WEr[1].x, m0); m1 = fmaf(ea.y, WEr[1].y, m1);   \
                m0 = fmaf(ea.z, WEr[2].x, m0); m1 = fmaf(ea.z, WEr[2].y, m1);   \
                m0 = fmaf(ea.w, WEr[3].x, m0); m1 = fmaf(ea.w, WEr[3].y, m1);   \
                s0 += m0; s1 += m1;                                             \
                q0 = fmaf(m0, m0, q0); q1 = fmaf(m1, m1, q1);                   \
                mn0 = fminf(mn0, m0); mn1 = fminf(mn1, m1);                     \
                mx0 = fmaxf(mx0, m0); mx1 = fmaxf(mx1, m1);                     \
            }
            PROC(eA, vA) PROC(eB, vB) PROC(eC, vC) PROC(eD, vD)
        }
        for (; i < end; i++) {
            int sA = g_src[i];
            float4 eA = g_ea[i];
            float2 vA = ((const float2*)(g_v + (size_t)sA * 64))[lane];
            PROC(eA, vA)
        }
#undef PROC

        float2 u2 = ((const float2*)(g_u + (size_t)n * 64))[lane];
        float sh0 = u2.x + BEr.x, sh1 = u2.y + BEr.y;

        float deg = fmaxf((float)cnt, 1.f);
        float inv = 1.f / deg;
        float mvc0 = s0 * inv, mvc1 = s1 * inv;
        float std0 = sqrtf(fmaxf(q0 * inv - mvc0 * mvc0, 0.f) + STD_EPS);
        float std1 = sqrtf(fmaxf(q1 * inv - mvc1 * mvc1, 0.f) + STD_EPS);

        float mean0, mean1;
        if (cnt == 0) {
            mean0 = mean1 = 0.f;
            mn0 = mn1 = mx0 = mx1 = 0.f;
        } else {
            mean0 = mvc0 + sh0; mean1 = mvc1 + sh1;
            mn0 += sh0; mn1 += sh1;
            mx0 += sh0; mx1 += sh1;
        }

        float logdeg = logf(deg + 1.f);
        float2 sc = make_float2(logdeg * (1.f / LOG17), LOG17 / logdeg);

        float* ag = g_agg + (size_t)n * 256 + t * 64;
        ((float2*)(ag))[o0 >> 1]      = make_float2(mean0, mean1);
        ((float2*)(ag + 16))[o0 >> 1] = make_float2(mn0, mn1);
        ((float2*)(ag + 32))[o0 >> 1] = make_float2(mx0, mx1);
        ((float2*)(ag + 48))[o0 >> 1] = make_float2(std0, std1);
        if (lane == 0) g_scal[n] = sc;
    }
}

// ---------------- K8: post-MLP + linear + ReLU (4-node register blocking) ----------------
// smem layout (floats):
//   w_s   [208][64]            13312   (w_s[f*64+g] = W_post[t(g)][f][g%16])
//   wl_s  [64][64]              4096
//   in_s  16 warps * 4t*81*4n  20736   (tower stride 324 -> bank rotation)
//   post_s 16 warps * 4n*64     4096
#define SM_WL   13312
#define SM_IN   17408
#define SM_POST 38144
#define SM_TOTF 42240

__global__ void __launch_bounds__(512, 1) k_post(
    const float* __restrict__ x, const float* __restrict__ Wpost,
    const float* __restrict__ bpost, const float* __restrict__ Wlin,
    const float* __restrict__ blin, float* __restrict__ out, int N)
{
    extern __shared__ float sm[];
    float* w_s = sm;
    float* wl_s = sm + SM_WL;
    int tid = threadIdx.x;

    for (int i = tid; i < 13312; i += 512) {
        int f = i >> 6, g = i & 63;
        w_s[i] = Wpost[((g >> 4) * 208 + f) * 16 + (g & 15)];
    }
    for (int i = tid; i < 4096; i += 512) wl_s[i] = Wlin[i];
    __syncthreads();

    int lane = tid & 31, wid = tid >> 5;
    int t = lane >> 3, q = lane & 7, o0 = (2 * lane) & 15, g = 2 * lane;
    float* my_in = sm + SM_IN + wid * 1296;
    float* my_post = sm + SM_POST + wid * 256;
    int base = blockIdx.x * 64 + wid * 4;

    // ---- stage 4 nodes: x + agg into [t][f][node] ----
    float samp[4], satt[4];
#pragma unroll
    for (int nn = 0; nn < 4; nn++) {
        int node = min(base + nn, N - 1);
        float2 xv = ((const float2*)(x + (size_t)node * 64))[lane];
        my_in[t * 324 + o0 * 4 + nn] = xv.x;
        my_in[t * 324 + (o0 + 1) * 4 + nn] = xv.y;
        const float* ap = g_agg + (size_t)node * 256 + t * 64;
#pragma unroll
        for (int m = 0; m < 8; m++) {
            float av = ap[q + 8 * m];                        // strided: 4x32B sectors/warp
            my_in[t * 324 + (16 + q + 8 * m) * 4 + nn] = av; // ~2-way bank conflict
        }
        float2 sc = g_scal[node];
        samp[nn] = sc.x; satt[nn] = sc.y;
    }
    __syncwarp();

    const float2* w2 = (const float2*)w_s;
    const float4* iv4 = (const float4*)(my_in + t * 324);

    float2 bp2 = ((const float2*)bpost)[lane];
    float acc0[4], acc1[4];
#pragma unroll
    for (int nn = 0; nn < 4; nn++) { acc0[nn] = bp2.x; acc1[nn] = bp2.y; }

    // seg1: f 0..79  (x + raw agg, scale 1)
#pragma unroll 8
    for (int f = 0; f < 80; f++) {
        float4 iv = iv4[f];
        float2 w = w2[f * 32 + lane];
        acc0[0] = fmaf(iv.x, w.x, acc0[0]); acc1[0] = fmaf(iv.x, w.y, acc1[0]);
        acc0[1] = fmaf(iv.y, w.x, acc0[1]); acc1[1] = fmaf(iv.y, w.y, acc1[1]);
        acc0[2] = fmaf(iv.z, w.x, acc0[2]); acc1[2] = fmaf(iv.z, w.y, acc1[2]);
        acc0[3] = fmaf(iv.w, w.x, acc0[3]); acc1[3] = fmaf(iv.w, w.y, acc1[3]);
    }
    // seg2: f 80..143  (agg * samp)
    {
        float b0[4] = {0, 0, 0, 0}, b1[4] = {0, 0, 0, 0};
#pragma unroll 8
        for (int f = 80; f < 144; f++) {
            float4 iv = iv4[f - 64];
            float2 w = w2[f * 32 + lane];
            b0[0] = fmaf(iv.x, w.x, b0[0]); b1[0] = fmaf(iv.x, w.y, b1[0]);
            b0[1] = fmaf(iv.y, w.x, b0[1]); b1[1] = fmaf(iv.y, w.y, b1[1]);
            b0[2] = fmaf(iv.z, w.x, b0[2]); b1[2] = fmaf(iv.z, w.y, b1[2]);
            b0[3] = fmaf(iv.w, w.x, b0[3]); b1[3] = fmaf(iv.w, w.y, b1[3]);
        }
#pragma unroll
        for (int nn = 0; nn < 4; nn++) {
            acc0[nn] = fmaf(samp[nn], b0[nn], acc0[nn]);
            acc1[nn] = fmaf(samp[nn], b1[nn], acc1[nn]);
        }
    }
    // seg3: f 144..207  (agg * satt)
    {
        float b0[4] = {0, 0, 0, 0}, b1[4] = {0, 0, 0, 0};
#pragma unroll 8
        for (int f = 144; f < 208; f++) {
            float4 iv = iv4[f - 128];
            float2 w = w2[f * 32 + lane];
            b0[0] = fmaf(iv.x, w.x, b0[0]); b1[0] = fmaf(iv.x, w.y, b1[0]);
            b0[1] = fmaf(iv.y, w.x, b0[1]); b1[1] = fmaf(iv.y, w.y, b1[1]);
            b0[2] = fmaf(iv.z, w.x, b0[2]); b1[2] = fmaf(iv.z, w.y, b1[2]);
            b0[3] = fmaf(iv.w, w.x, b0[3]); b1[3] = fmaf(iv.w, w.y, b1[3]);
        }
#pragma unroll
        for (int nn = 0; nn < 4; nn++) {
            acc0[nn] = fmaf(satt[nn], b0[nn], acc0[nn]);
            acc1[nn] = fmaf(satt[nn], b1[nn], acc1[nn]);
        }
    }

    // stage post outputs
#pragma unroll
    for (int nn = 0; nn < 4; nn++)
        ((float2*)(my_post + nn * 64))[lane] = make_float2(acc0[nn], acc1[nn]);
    __syncwarp();

    // final 64x64 linear + ReLU
    float2 bl2 = ((const float2*)blin)[lane];
    float y0[4], y1[4];
#pragma unroll
    for (int nn = 0; nn < 4; nn++) { y0[nn] = bl2.x; y1[nn] = bl2.y; }
    const float2* wl2 = (const float2*)wl_s;
#pragma unroll 8
    for (int k = 0; k < 64; k++) {
        float2 w = wl2[k * 32 + lane];
#pragma unroll
        for (int nn = 0; nn < 4; nn++) {
            float p = my_post[nn * 64 + k];
            y0[nn] = fmaf(p, w.x, y0[nn]);
            y1[nn] = fmaf(p, w.y, y1[nn]);
        }
    }
#pragma unroll
    for (int nn = 0; nn < 4; nn++) {
        int node = base + nn;
        if (node < N)
            ((float2*)(out + (size_t)node * 64))[lane] =
                make_float2(fmaxf(y0[nn], 0.f), fmaxf(y1[nn], 0.f));
    }
}

extern "C" void kernel_launch(void* const* d_in, const int* in_sizes, int n_in,
                              void* d_out, int out_size)
{
    const float* x      = (const float*)d_in[0];
    const int*   ei     = (const int*)d_in[1];
    const float* eattr  = (const float*)d_in[2];
    const float* W_edge = (const float*)d_in[3];
    const float* b_edge = (const float*)d_in[4];
    const float* W_pre  = (const float*)d_in[5];
    const float* b_pre  = (const float*)d_in[6];
    const float* W_post = (const float*)d_in[7];
    const float* b_post = (const float*)d_in[8];
    const float* W_lin  = (const float*)d_in[9];
    const float* b_lin  = (const float*)d_in[10];
    float* out = (float*)d_out;

    const int N = in_sizes[0] / 64;
    const int E = in_sizes[1] / 2;

    cudaFuncSetAttribute(k_post, cudaFuncAttributeMaxDynamicSharedMemorySize,
                         SM_TOTF * 4);

    k_zero<<<(N + 255) / 256, 256>>>(N);
    k_hist<<<(E + 255) / 256, 256>>>(ei, E);
    k_scan<<<1, 1024>>>(N, E);
    k_fold<<<1, 256>>>(W_edge, b_edge, W_pre, b_pre);
    k_uv<<<2500, 256>>>(x, W_pre, N);
    k_scatter<<<(E + 255) / 256, 256>>>(ei, eattr, E);
    k_agg<<<3125, 256>>>(N);
    k_post<<<(N + 63) / 64, 512, SM_TOTF * 4>>>(x, W_post, b_post, W_lin, b_lin, out, N);
}

// round 6
// speedup vs baseline: 3.6224x; 1.1491x over previous
#include <cuda_runtime.h>
#include <cuda_bf16.h>
#include <cstdint>

#define NN 100000
#define EE 1600000
#define LOG17 2.8332133440562162f
#define STD_EPS 1e-5f

// ---- scratch (static device arrays; no allocation anywhere) ----
__device__ int    g_cnt[NN];
__device__ int    g_off[NN + 1];
__device__ int    g_pos[NN];
__device__ int    g_src[EE];
__device__ float4 g_ea[EE];
__device__ float  g_v[(size_t)NN * 64];
__device__ float  g_WE[256];                 // [t][4][16] folded edge weights
__device__ float  g_BE[64];                  // [t][16]   folded bias (b_edge@C + b_pre)

// ---------------- K1: zero histogram ----------------
__global__ void k_zero(int n) {
    int i = blockIdx.x * blockDim.x + threadIdx.x;
    if (i < n) g_cnt[i] = 0;
}

// ---------------- K2: histogram over dst ----------------
__global__ void k_hist(const int* __restrict__ ei, int E) {
    int i = blockIdx.x * blockDim.x + threadIdx.x;
    if (i < E) atomicAdd(&g_cnt[ei[E + i]], 1);
}

// ---------------- K3: single-block exclusive scan ----------------
__global__ void k_scan(int N, int E) {
    __shared__ int sh[1024];
    int tid = threadIdx.x;
    int C = (N + 1023) / 1024;
    int s = tid * C;
    int e = min(s + C, N);
    int sum = 0;
    for (int i = s; i < e; i++) sum += g_cnt[i];
    sh[tid] = sum;
    __syncthreads();
    for (int off = 1; off < 1024; off <<= 1) {
        int v = (tid >= off) ? sh[tid - off] : 0;
        __syncthreads();
        sh[tid] += v;
        __syncthreads();
    }
    int run = sh[tid] - sum;  // exclusive
    for (int i = s; i < e; i++) {
        g_off[i] = run;
        g_pos[i] = run;
        run += g_cnt[i];
    }
    if (tid == 0) g_off[N] = E;
}

// ---------------- K4: v = x@B per tower; block 0 also folds edge encoder ----------------
__global__ void __launch_bounds__(256) k_v(const float* __restrict__ x,
                                           const float* __restrict__ We,
                                           const float* __restrict__ be,
                                           const float* __restrict__ Wp,
                                           const float* __restrict__ bp, int N) {
    // fold: WE[t][d][o] = sum_k W_edge[d][k] * W_pre[t][32+k][o]
    //       BE[t][o]    = b_pre[t][o] + sum_k b_edge[k] * W_pre[t][32+k][o]
    if (blockIdx.x == 0) {
        int tid = threadIdx.x;
        int t = tid >> 6, d = (tid >> 4) & 3, o = tid & 15;
        float s = 0.f;
#pragma unroll
        for (int k = 0; k < 16; k++)
            s += We[d * 16 + k] * Wp[(t * 48 + 32 + k) * 16 + o];
        g_WE[t * 64 + d * 16 + o] = s;
        if (d == 0) {
            float b = bp[t * 16 + o];
#pragma unroll
            for (int k = 0; k < 16; k++)
                b += be[k] * Wp[(t * 48 + 32 + k) * 16 + o];
            g_BE[t * 16 + o] = b;
        }
    }

    __shared__ float B64[16 * 64];   // [k][g] where g=t*16+o
    int tid = threadIdx.x;
    for (int i = tid; i < 1024; i += 256) {
        int k = i >> 6, g = i & 63, t = g >> 4, o = g & 15;
        B64[i] = Wp[(t * 48 + 16 + k) * 16 + o];
    }
    __syncthreads();
    int lane = tid & 31, wid = tid >> 5;
    int warp = blockIdx.x * 8 + wid, nw = gridDim.x * 8;
    const float2* B2 = (const float2*)B64;
    for (int n = warp; n < N; n += nw) {
        float2 xv = ((const float2*)(x + (size_t)n * 64))[lane];
        float v0 = 0.f, v1 = 0.f;
#pragma unroll
        for (int k = 0; k < 16; k++) {
            int srcl = (lane & 24) | (k >> 1);
            float xk = __shfl_sync(0xffffffffu, (k & 1) ? xv.y : xv.x, srcl);
            float2 b = B2[k * 32 + lane];
            v0 = fmaf(xk, b.x, v0); v1 = fmaf(xk, b.y, v1);
        }
        ((float2*)(g_v + (size_t)n * 64))[lane] = make_float2(v0, v1);
    }
}

// ---------------- K5: CSR scatter (src + edge_attr reordered by dst) ----------------
__global__ void k_scatter(const int* __restrict__ ei, const float* __restrict__ eattr, int E) {
    int e = blockIdx.x * blockDim.x + threadIdx.x;
    if (e < E) {
        int dst = ei[E + e];
        int p = atomicAdd(&g_pos[dst], 1);
        g_src[p] = ei[e];
        g_ea[p] = ((const float4*)eattr)[e];
    }
}

// ---------------- K6: fused agg + post-MLP + linear + ReLU (persistent) ----------------
// smem layout (floats):
//   w_s   [208][64]            13312
//   wl_s  [64][64]              4096
//   A_s   [16][64]              1024  (W_pre A block for u = x@A)
//   in_s  16 warps * [4t][81][4n] 20736
//   post_s 16 warps * [4n][64]   4096
#define SM_WL   13312
#define SM_A    17408
#define SM_IN   18432
#define SM_POST 39168
#define SM_TOTF 43264

__global__ void __launch_bounds__(512) k_node(
    const float* __restrict__ x, const float* __restrict__ Wp,
    const float* __restrict__ Wpost, const float* __restrict__ bpost,
    const float* __restrict__ Wlin, const float* __restrict__ blin,
    float* __restrict__ out, int N)
{
    extern __shared__ float sm[];
    float* w_s = sm;
    float* wl_s = sm + SM_WL;
    float* A_s = sm + SM_A;
    int tid = threadIdx.x;

    for (int i = tid; i < 13312; i += 512) {
        int f = i >> 6, g = i & 63;
        w_s[i] = Wpost[((g >> 4) * 208 + f) * 16 + (g & 15)];
    }
    for (int i = tid; i < 4096; i += 512) wl_s[i] = Wlin[i];
    for (int i = tid; i < 1024; i += 512) {
        int k = i >> 6, g = i & 63, t = g >> 4, o = g & 15;
        A_s[i] = Wp[(t * 48 + k) * 16 + o];
    }
    __syncthreads();

    const int lane = tid & 31, wid = tid >> 5;
    const int t = lane >> 3, o0 = (2 * lane) & 15;
    float* my_in = sm + SM_IN + wid * 1296;
    float* my_post = sm + SM_POST + wid * 256;
    const float2* A2 = (const float2*)A_s;

    float2 WEr[4];
#pragma unroll
    for (int d = 0; d < 4; d++)
        WEr[d] = ((const float2*)g_WE)[(t * 64 + d * 16 + o0) >> 1];
    const float2 BEr = ((const float2*)g_BE)[lane];
    const float2 bp2 = ((const float2*)bpost)[lane];
    const float2 bl2 = ((const float2*)blin)[lane];
    const float2* w2 = (const float2*)w_s;
    const float2* wl2 = (const float2*)wl_s;
    const float4* iv4 = (const float4*)(my_in + t * 324);

    const int step = gridDim.x * 64;
    for (int base = blockIdx.x * 64 + wid * 4; base < N; base += step) {
        float samp[4], satt[4];

        // ---- Phase A: aggregate 4 nodes, stage into smem ----
#pragma unroll
        for (int nn = 0; nn < 4; nn++) {
            const int node = min(base + nn, N - 1);

            // x row + inline u = x@A (shfl broadcast of x features)
            const float2 xv = ((const float2*)(x + (size_t)node * 64))[lane];
            float u0 = 0.f, u1 = 0.f;
#pragma unroll
            for (int k = 0; k < 16; k++) {
                int srcl = (lane & 24) | (k >> 1);
                float xk = __shfl_sync(0xffffffffu, (k & 1) ? xv.y : xv.x, srcl);
                float2 a = A2[k * 32 + lane];
                u0 = fmaf(xk, a.x, u0); u1 = fmaf(xk, a.y, u1);
            }

            // aggregate incident edges: m = v[src] + ea@WE (per-lane 2 features)
            const int be_ = g_off[node], en_ = g_off[node + 1];
            const int cnt = en_ - be_;
            float s0 = 0.f, s1 = 0.f, q0 = 0.f, q1 = 0.f;
            float mn0 = 1e30f, mn1 = 1e30f, mx0 = -1e30f, mx1 = -1e30f;
            int i = be_;
#define PROC(ea, vv)                                                            \
            {                                                                   \
                float m0 = vv.x, m1 = vv.y;                                     \
                m0 = fmaf(ea.x, WEr[0].x, m0); m1 = fmaf(ea.x, WEr[0].y, m1);   \
                m0 = fmaf(ea.y, WEr[1].x, m0); m1 = fmaf(ea.y, WEr[1].y, m1);   \
                m0 = fmaf(ea.z, WEr[2].x, m0); m1 = fmaf(ea.z, WEr[2].y, m1);   \
                m0 = fmaf(ea.w, WEr[3].x, m0); m1 = fmaf(ea.w, WEr[3].y, m1);   \
                s0 += m0; s1 += m1;                                             \
                q0 = fmaf(m0, m0, q0); q1 = fmaf(m1, m1, q1);                   \
                mn0 = fminf(mn0, m0); mn1 = fminf(mn1, m1);                     \
                mx0 = fmaxf(mx0, m0); mx1 = fmaxf(mx1, m1);                     \
            }
            for (; i + 4 <= en_; i += 4) {
                int sA = g_src[i], sB = g_src[i + 1], sC = g_src[i + 2], sD = g_src[i + 3];
                float4 eA = g_ea[i], eB = g_ea[i + 1], eC = g_ea[i + 2], eD = g_ea[i + 3];
                float2 vA = ((const float2*)(g_v + (size_t)sA * 64))[lane];
                float2 vB = ((const float2*)(g_v + (size_t)sB * 64))[lane];
                float2 vC = ((const float2*)(g_v + (size_t)sC * 64))[lane];
                float2 vD = ((const float2*)(g_v + (size_t)sD * 64))[lane];
                PROC(eA, vA) PROC(eB, vB) PROC(eC, vC) PROC(eD, vD)
            }
            for (; i < en_; i++) {
                int sA = g_src[i];
                float4 eA = g_ea[i];
                float2 vA = ((const float2*)(g_v + (size_t)sA * 64))[lane];
                PROC(eA, vA)
            }
#undef PROC

            const float sh0 = u0 + BEr.x, sh1 = u1 + BEr.y;
            const float deg = fmaxf((float)cnt, 1.f);
            const float inv = 1.f / deg;
            const float mvc0 = s0 * inv, mvc1 = s1 * inv;
            const float std0 = sqrtf(fmaxf(q0 * inv - mvc0 * mvc0, 0.f) + STD_EPS);
            const float std1 = sqrtf(fmaxf(q1 * inv - mvc1 * mvc1, 0.f) + STD_EPS);
            float mean0, mean1;
            if (cnt == 0) {
                mean0 = mean1 = 0.f;
                mn0 = mn1 = mx0 = mx1 = 0.f;
            } else {
                mean0 = mvc0 + sh0; mean1 = mvc1 + sh1;
                mn0 += sh0; mn1 += sh1;
                mx0 += sh0; mx1 += sh1;
            }
            const float logdeg = logf(deg + 1.f);
            samp[nn] = logdeg * (1.f / LOG17);
            satt[nn] = LOG17 / logdeg;

            float* row = my_in + t * 324;
            row[o0 * 4 + nn] = xv.x;              row[(o0 + 1) * 4 + nn] = xv.y;
            row[(16 + o0) * 4 + nn] = mean0;      row[(16 + o0 + 1) * 4 + nn] = mean1;
            row[(32 + o0) * 4 + nn] = mn0;        row[(32 + o0 + 1) * 4 + nn] = mn1;
            row[(48 + o0) * 4 + nn] = mx0;        row[(48 + o0 + 1) * 4 + nn] = mx1;
            row[(64 + o0) * 4 + nn] = std0;       row[(64 + o0 + 1) * 4 + nn] = std1;
        }
        __syncwarp();

        // ---- Phase B: post MLP (segments share staged features via scalers) ----
        float acc0[4], acc1[4];
#pragma unroll
        for (int nn = 0; nn < 4; nn++) { acc0[nn] = bp2.x; acc1[nn] = bp2.y; }

#pragma unroll 8
        for (int f = 0; f < 80; f++) {
            float4 iv = iv4[f];
            float2 w = w2[f * 32 + lane];
            acc0[0] = fmaf(iv.x, w.x, acc0[0]); acc1[0] = fmaf(iv.x, w.y, acc1[0]);
            acc0[1] = fmaf(iv.y, w.x, acc0[1]); acc1[1] = fmaf(iv.y, w.y, acc1[1]);
            acc0[2] = fmaf(iv.z, w.x, acc0[2]); acc1[2] = fmaf(iv.z, w.y, acc1[2]);
            acc0[3] = fmaf(iv.w, w.x, acc0[3]); acc1[3] = fmaf(iv.w, w.y, acc1[3]);
        }
        {
            float b0[4] = {0, 0, 0, 0}, b1[4] = {0, 0, 0, 0};
#pragma unroll 8
            for (int f = 80; f < 144; f++) {
                float4 iv = iv4[f - 64];
                float2 w = w2[f * 32 + lane];
                b0[0] = fmaf(iv.x, w.x, b0[0]); b1[0] = fmaf(iv.x, w.y, b1[0]);
                b0[1] = fmaf(iv.y, w.x, b0[1]); b1[1] = fmaf(iv.y, w.y, b1[1]);
                b0[2] = fmaf(iv.z, w.x, b0[2]); b1[2] = fmaf(iv.z, w.y, b1[2]);
                b0[3] = fmaf(iv.w, w.x, b0[3]); b1[3] = fmaf(iv.w, w.y, b1[3]);
            }
#pragma unroll
            for (int nn = 0; nn < 4; nn++) {
                acc0[nn] = fmaf(samp[nn], b0[nn], acc0[nn]);
                acc1[nn] = fmaf(samp[nn], b1[nn], acc1[nn]);
            }
        }
        {
            float b0[4] = {0, 0, 0, 0}, b1[4] = {0, 0, 0, 0};
#pragma unroll 8
            for (int f = 144; f < 208; f++) {
                float4 iv = iv4[f - 128];
                float2 w = w2[f * 32 + lane];
                b0[0] = fmaf(iv.x, w.x, b0[0]); b1[0] = fmaf(iv.x, w.y, b1[0]);
                b0[1] = fmaf(iv.y, w.x, b0[1]); b1[1] = fmaf(iv.y, w.y, b1[1]);
                b0[2] = fmaf(iv.z, w.x, b0[2]); b1[2] = fmaf(iv.z, w.y, b1[2]);
                b0[3] = fmaf(iv.w, w.x, b0[3]); b1[3] = fmaf(iv.w, w.y, b1[3]);
            }
#pragma unroll
            for (int nn = 0; nn < 4; nn++) {
                acc0[nn] = fmaf(satt[nn], b0[nn], acc0[nn]);
                acc1[nn] = fmaf(satt[nn], b1[nn], acc1[nn]);
            }
        }

#pragma unroll
        for (int nn = 0; nn < 4; nn++)
            ((float2*)(my_post + nn * 64))[lane] = make_float2(acc0[nn], acc1[nn]);
        __syncwarp();

        // ---- final 64x64 linear + ReLU ----
        float y0[4], y1[4];
#pragma unroll
        for (int nn = 0; nn < 4; nn++) { y0[nn] = bl2.x; y1[nn] = bl2.y; }
#pragma unroll 8
        for (int k = 0; k < 64; k++) {
            float2 w = wl2[k * 32 + lane];
#pragma unroll
            for (int nn = 0; nn < 4; nn++) {
                float p = my_post[nn * 64 + k];
                y0[nn] = fmaf(p, w.x, y0[nn]);
                y1[nn] = fmaf(p, w.y, y1[nn]);
            }
        }
#pragma unroll
        for (int nn = 0; nn < 4; nn++) {
            int node = base + nn;
            if (node < N)
                ((float2*)(out + (size_t)node * 64))[lane] =
                    make_float2(fmaxf(y0[nn], 0.f), fmaxf(y1[nn], 0.f));
        }
        __syncwarp();
    }
}

extern "C" void kernel_launch(void* const* d_in, const int* in_sizes, int n_in,
                              void* d_out, int out_size)
{
    const float* x      = (const float*)d_in[0];
    const int*   ei     = (const int*)d_in[1];
    const float* eattr  = (const float*)d_in[2];
    const float* W_edge = (const float*)d_in[3];
    const float* b_edge = (const float*)d_in[4];
    const float* W_pre  = (const float*)d_in[5];
    const float* b_pre  = (const float*)d_in[6];
    const float* W_post = (const float*)d_in[7];
    const float* b_post = (const float*)d_in[8];
    const float* W_lin  = (const float*)d_in[9];
    const float* b_lin  = (const float*)d_in[10];
    float* out = (float*)d_out;

    const int N = in_sizes[0] / 64;
    const int E = in_sizes[1] / 2;

    cudaFuncSetAttribute(k_node, cudaFuncAttributeMaxDynamicSharedMemorySize,
                         SM_TOTF * 4);

    k_zero<<<(N + 255) / 256, 256>>>(N);
    k_hist<<<(E + 255) / 256, 256>>>(ei, E);
    k_scan<<<1, 1024>>>(N, E);
    k_v<<<2500, 256>>>(x, W_edge, b_edge, W_pre, b_pre, N);
    k_scatter<<<(E + 255) / 256, 256>>>(ei, eattr, E);
    k_node<<<148, 512, SM_TOTF * 4>>>(x, W_pre, W_post, b_post, W_lin, b_lin, out, N);
}